// round 7
// baseline (speedup 1.0000x reference)
#include <cuda_runtime.h>
#include <stdint.h>

// Problem constants (match reference)
#define BB      1024        // batch
#define PP      512         // patches
#define KK      128         // dim
#define NM      819         // int(B*0.8)
#define NMR     921         // NM + int(B*0.1)
#define MAXC    76          // int(0.15*4096/8)
#define NTOT    67108864    // B*P*K
#define I_OFF   67108864
#define MT_OFF  (67108864 + 1024*76)

// Device globals (no allocation allowed)
__device__ int g_mode;

// ---------------------------------------------------------------------------
// threefry2x32, exactly as in jax/_src/prng.py (5 groups of 4 rounds)
// ---------------------------------------------------------------------------
__device__ __forceinline__ uint2 tf2x32(uint32_t k0, uint32_t k1,
                                        uint32_t x0, uint32_t x1) {
    uint32_t k2 = k0 ^ k1 ^ 0x1BD11BDAu;
    x0 += k0; x1 += k1;
#define TFR(r) { x0 += x1; x1 = (x1 << (r)) | (x1 >> (32 - (r))); x1 ^= x0; }
    TFR(13) TFR(15) TFR(26) TFR(6)
    x0 += k1; x1 += k2 + 1u;
    TFR(17) TFR(29) TFR(16) TFR(24)
    x0 += k2; x1 += k0 + 2u;
    TFR(13) TFR(15) TFR(26) TFR(6)
    x0 += k0; x1 += k1 + 3u;
    TFR(17) TFR(29) TFR(16) TFR(24)
    x0 += k1; x1 += k2 + 4u;
    TFR(13) TFR(15) TFR(26) TFR(6)
    x0 += k2; x1 += k0 + 5u;
#undef TFR
    return make_uint2(x0, x1);
}

// Partitionable-threefry 32-bit random bits for element index i (i < 2^32):
// counter = (0, i), output = out0 ^ out1.
__device__ __forceinline__ uint32_t rbits32(uint32_t k0, uint32_t k1, uint32_t i) {
    uint2 r = tf2x32(k0, k1, 0u, i);
    return r.x ^ r.y;
}

// ---------------------------------------------------------------------------
// k_mode: ONE block, 512 threads. Stable-sort rank of all 1024 permutation
// elements via bucket-radix counting (2 elems/thread) -> mask_type + g_mode.
// rank(i) = #{j : (key_j, j) < (key_i, i)} == stable-sort position, exactly.
// ---------------------------------------------------------------------------
__global__ void k_mode(float* __restrict__ mt_out) {
    __shared__ unsigned long long pkeys[2*PP];
    __shared__ int hist[256];
    __shared__ int pfx[257];
    __shared__ uint32_t ssub[2];
    int p = threadIdx.x;
    if (p == 0) {
        uint2 kp  = tf2x32(0u, 42u, 0u, 0u);      // split(key(42),3)[0]
        uint2 sub = tf2x32(kp.x, kp.y, 0u, 1u);   // _shuffle's subkey
        ssub[0] = sub.x; ssub[1] = sub.y;
    }
    if (p < 256) hist[p] = 0;
    __syncthreads();
    unsigned long long pk[2];
    int pbkt[2], pofs[2];
    uint32_t s0 = ssub[0], s1 = ssub[1];
#pragma unroll
    for (int rr = 0; rr < 2; rr++) {
        int j = p + (rr << 9);
        uint32_t bits = rbits32(s0, s1, (uint32_t)j);
        pk[rr]   = ((unsigned long long)bits << 10) | (unsigned)j;
        pbkt[rr] = (int)(bits >> 24);
        pofs[rr] = atomicAdd(&hist[pbkt[rr]], 1);
    }
    __syncthreads();
    if (p < 32) {
        int base = p * 8;                     // 32*8 = 256
        int loc[8];
        int s = 0;
#pragma unroll
        for (int i = 0; i < 8; i++) { loc[i] = s; s += hist[base + i]; }
        int t = s;
#pragma unroll
        for (int o = 1; o < 32; o <<= 1) {
            int u = __shfl_up_sync(0xffffffffu, t, o);
            if (p >= o) t += u;
        }
        int excl = t - s;
#pragma unroll
        for (int i = 0; i < 8; i++) pfx[base + i] = excl + loc[i];
        if (p == 31) pfx[256] = t;
    }
    __syncthreads();
#pragma unroll
    for (int rr = 0; rr < 2; rr++)
        pkeys[pfx[pbkt[rr]] + pofs[rr]] = pk[rr];
    __syncthreads();
#pragma unroll
    for (int rr = 0; rr < 2; rr++) {
        int j = p + (rr << 9);
        int s2 = pfx[pbkt[rr]], e2 = pfx[pbkt[rr] + 1];
        int rank = s2;
        for (int q = s2; q < e2; q++) rank += (pkeys[q] < pk[rr]);
        int grp = (rank < NM) ? 0 : ((rank < NMR) ? 1 : 2);
        mt_out[j] = (float)grp;
        if (j == 0) g_mode = grp;
    }
}

// ---------------------------------------------------------------------------
// k_rows: 1024 blocks x 512 threads. Block b owns batch row b:
//   Prologue: exact bucket-radix stable-argsort rank -> sel (shared) + I_out.
//   Body:     stream the row's 512 KB (32 float4/thread, MLP-4 batches),
//             applying the mode-dependent replacement for selected patches.
// The prologue ALU hides under other resident blocks' memory streaming.
// ---------------------------------------------------------------------------
__global__ void __launch_bounds__(512) k_rows(
        const int* __restrict__ seq_len,
        float* __restrict__ I_out,
        const float* __restrict__ x, const float* __restrict__ pos,
        const float* __restrict__ wm, float* __restrict__ out) {
    __shared__ unsigned long long skeys[PP];
    __shared__ int hist[257];
    __shared__ int pfx[258];
    __shared__ uint32_t skey[4];           // ks0, ks1, kr0, kr1
    __shared__ unsigned char sel_sh[PP];
    int b = blockIdx.x;
    int p = threadIdx.x;
    if (p == 0) {
        uint2 ks = tf2x32(0u, 42u, 0u, 1u);   // split(key(42),3)[1]
        uint2 kr = tf2x32(0u, 42u, 0u, 2u);   // split(key(42),3)[2]
        skey[0] = ks.x; skey[1] = ks.y;
        skey[2] = kr.x; skey[3] = kr.y;
    }
    if (p < 257) hist[p] = 0;
    __syncthreads();

    // ---- prologue: row-score key + bucket (hash only if valid) ----
    int sl = seq_len[b];
    int nv = sl >> 3;  // seq_len // PATCH
    bool valid = (p < nv);
    uint32_t keyhi = 0x00800000u;          // +inf sentinel > any mantissa
    if (valid)
        // uniform(ks,(B,P)) ordering == ordering of 23-bit mantissa (bits>>9)
        keyhi = rbits32(skey[0], skey[1], (uint32_t)(b * PP + p)) >> 9;
    unsigned long long key = ((unsigned long long)keyhi << 32) | (unsigned)p;
    int bucket = valid ? (int)(keyhi >> 15) : 256;   // 0..255 valid, 256 invalid
    int ofs = atomicAdd(&hist[bucket], 1);
    __syncthreads();

    if (p < 32) {                           // exclusive scan over 257 buckets
        int base = p * 9;                   // 32*9 = 288 >= 258
        int loc[9];
        int s = 0;
#pragma unroll
        for (int i = 0; i < 9; i++) {
            int idx = base + i;
            int v = (idx < 257) ? hist[idx] : 0;
            loc[i] = s; s += v;
        }
        int t = s;
#pragma unroll
        for (int o = 1; o < 32; o <<= 1) {
            int u = __shfl_up_sync(0xffffffffu, t, o);
            if (p >= o) t += u;
        }
        int excl = t - s;
#pragma unroll
        for (int i = 0; i < 9; i++) {
            int idx = base + i;
            if (idx < 258) pfx[idx] = excl + loc[i];
        }
    }
    __syncthreads();

    int start = pfx[bucket];
    skeys[start + ofs] = key;               // bucket-grouped scatter
    __syncthreads();

    int r;
    if (valid) {                             // exact stable rank
        int end = pfx[bucket + 1];
        r = start;
        for (int j = start; j < end; j++) r += (skeys[j] < key);
    } else {
        r = start;   // start = n_valid >= n_corr -> never selected
    }
    // n_corr = floor(0.15f * float(seq_len) / 8.0f), f32 rounding as in JAX
    int nc = (int)floorf(0.15f * (float)sl / 8.0f);
    bool s_here = (r < nc);
    sel_sh[p] = s_here ? 1 : 0;
    if (s_here)              I_out[b * MAXC + r] = (float)p;  // I[b][rank]=patch
    if (p >= nc && p < MAXC) I_out[b * MAXC + p] = -1.0f;     // pad slots

    int mode = g_mode;                       // broadcast load (L2-hot)
    uint32_t kr0 = skey[2], kr1 = skey[3];
    __syncthreads();

    // ---- body: stream this row (16384 float4, 32 per thread) ----
    const float4* xr  = (const float4*)x   + ((long)b << 14);
    float4*       orow = (float4*)out      + ((long)b << 14);
#pragma unroll
    for (int g = 0; g < 8; g++) {
        int t0 = (g << 11) + p;              // t_local = g*2048 + q*512 + p
        unsigned char sv[4];
#pragma unroll
        for (int q = 0; q < 4; q++)
            sv[q] = sel_sh[(t0 + (q << 9)) >> 5];   // patch = t_local>>5
#pragma unroll
        for (int q = 0; q < 4; q++) {
            int tl = t0 + (q << 9);
            float4 o;
            if (!sv[q] || mode == 2) {
                o = xr[tl];
            } else {
                float4 po = *(const float4*)(pos + ((tl << 2) & 65535));
                if (mode == 0) {
                    float4 w = *(const float4*)(wm + ((tl << 2) & 127));
                    o = make_float4(w.x + po.x, w.y + po.y,
                                    w.z + po.z, w.w + po.w);
                } else {
                    uint32_t eg = (uint32_t)(((long)b << 16) + (tl << 2));
                    float u[4];
#pragma unroll
                    for (int qq = 0; qq < 4; qq++) {
                        uint32_t bits = rbits32(kr0, kr1, eg + qq);
                        u[qq] = __uint_as_float((bits >> 9) | 0x3f800000u) - 1.0f;
                    }
                    o = make_float4(u[0] + po.x, u[1] + po.y,
                                    u[2] + po.z, u[3] + po.w);
                }
            }
            orow[tl] = o;
        }
    }
}

// ---------------------------------------------------------------------------
extern "C" void kernel_launch(void* const* d_in, const int* in_sizes, int n_in,
                              void* d_out, int out_size) {
    const float* x   = (const float*)d_in[0];
    const float* pos = (const float*)d_in[1];
    const float* wm  = (const float*)d_in[2];
    const int* sl    = (const int*)d_in[3];
    float* out = (float*)d_out;

    k_mode<<<1, PP>>>(out + MT_OFF);
    k_rows<<<BB, PP>>>(sl, out + I_OFF, x, pos, wm, out);
}